// round 9
// baseline (speedup 1.0000x reference)
#include <cuda_runtime.h>
#include <cstdint>

#define T_LEN   32768
#define NROWS   1024
#define NT      64                      // 2 warps per block (one row per block)
#define IT      16                      // items per lane
#define SUBC    512                     // elements per warp per chunk
#define CELEMS  1024                    // elements per chunk (2 warps)
#define NCHUNK  (T_LEN / CELEMS)        // 32 chunks per row
#define STAGES  4
#define F4W     128                     // float4 per tensor per warp-subchunk
#define REG_F4  (2 * F4W)               // P+Q region per warp per stage
#define STAGE_F4 (2 * REG_F4)           // both warps
#define SMEM_F4  (STAGES * STAGE_F4)    // 2048 float4 = 32 KB

__device__ double g_partial[NROWS];
__device__ unsigned int g_count;

__device__ __forceinline__ void cp16(uint32_t dst, const float4* src) {
    asm volatile("cp.async.cg.shared.global [%0], [%1], 16;" :: "r"(dst), "l"(src));
}
__device__ __forceinline__ void cp_commit() {
    asm volatile("cp.async.commit_group;" ::: "memory");
}
template <int N>
__device__ __forceinline__ void cp_wait() {
    asm volatile("cp.async.wait_group %0;" :: "n"(N) : "memory");
}
__device__ __forceinline__ int swz(int v) { return v ^ ((v >> 3) & 7); }

__global__ void __launch_bounds__(NT, 7)
wass_kernel(const float* __restrict__ yp, const float* __restrict__ yt,
            float* __restrict__ out) {
    __shared__ float4 smem[SMEM_F4];
    __shared__ float tot[2][2];          // ping-pong cross-warp subtotals
    __shared__ double dsum[2];
    __shared__ bool is_last;

    const int tid  = threadIdx.x;
    const int lane = tid & 31;
    const int w    = tid >> 5;           // warp 0/1
    const int row  = blockIdx.x;

    const float4* __restrict__ p4 = (const float4*)(yp + (long)row * T_LEN);
    const float4* __restrict__ t4 = (const float4*)(yt + (long)row * T_LEN);
    const uint32_t sbase = (uint32_t)__cvta_generic_to_shared(smem);

    // Per-warp region base (in float4) for stage s.
    auto region = [&](int s) { return s * STAGE_F4 + w * REG_F4; };

    // Issue one stage for this warp (one commit group): 4 f4 per tensor per lane.
    auto issue = [&](int s, int chunk) {
        const int vbase = chunk * (CELEMS / 4) + w * F4W;  // warp's gmem f4 base
        const int rb = region(s);
        #pragma unroll
        for (int i = 0; i < 4; i++) {
            int v  = i * 32 + lane;
            int sw = swz(v);
            cp16(sbase + (uint32_t)(rb + sw) * 16u,       p4 + vbase + v);
            cp16(sbase + (uint32_t)(rb + F4W + sw) * 16u, t4 + vbase + v);
        }
        cp_commit();
    };

    // Prologue: chunks 0..2 into stages 0..2 (3 groups pending per warp).
    issue(0, 0); issue(1, 1); issue(2, 2);

    double dacc = 0.0;
    float  carry = 0.0f;

    for (int f = 0; f < NCHUNK; f++) {
        const int s = f & (STAGES - 1);

        cp_wait<STAGES - 2>();     // this warp's chunk-f group complete
        __syncwarp();

        // Refill last-consumed stage with chunk f+3 (race-free: consumed at f-1).
        const int nc = f + STAGES - 1;
        if (nc < NCHUNK) issue((s + STAGES - 1) & (STAGES - 1), nc);
        else             cp_commit();

        // Consume own region: lane reads 16 contiguous elements (4 float4).
        const int rb = region(s);
        float d[IT];
        #pragma unroll
        for (int j = 0; j < 4; j++) {
            int v  = lane * 4 + j;
            int sw = swz(v);
            float4 Pj = smem[rb + sw];
            float4 Qj = smem[rb + F4W + sw];
            d[4*j+0] = Pj.x - Qj.x;
            d[4*j+1] = Pj.y - Qj.y;
            d[4*j+2] = Pj.z - Qj.z;
            d[4*j+3] = Pj.w - Qj.w;
        }

        // Per-lane inclusive prefix + segment total.
        float pr[IT];
        pr[0] = d[0];
        #pragma unroll
        for (int k = 1; k < IT; k++) pr[k] = pr[k-1] + d[k];
        float seg = pr[IT-1];

        // Warp inclusive scan of segment sums.
        float inc = seg;
        #pragma unroll
        for (int o = 1; o < 32; o <<= 1) {
            float y = __shfl_up_sync(0xffffffffu, inc, o);
            if (lane >= o) inc += y;
        }
        float wtotal = __shfl_sync(0xffffffffu, inc, 31);

        // Cross-warp combine: one barrier per chunk, ping-pong buffer.
        const int par = f & 1;
        if (lane == 0) tot[par][w] = wtotal;
        __syncthreads();
        float t0 = tot[par][0];
        float t1 = tot[par][1];

        float base = carry + (w ? t0 : 0.0f) + (inc - seg);
        carry += t0 + t1;

        // Weighted |cumsum| accumulation, 2 independent FMA chains.
        const int idx0 = f * CELEMS + w * SUBC + lane * IT;
        const float w0 = (float)(T_LEN - idx0);
        float acc0 = 0.0f, acc1 = 0.0f;
        #pragma unroll
        for (int k = 0; k < IT; k += 2) {
            float r0 = base + pr[k];
            float r1 = base + pr[k+1];
            acc0 = fmaf(fabsf(r0), w0 - (float)k,       acc0);
            acc1 = fmaf(fabsf(r1), w0 - (float)(k + 1), acc1);
        }
        dacc += (double)(acc0 + acc1);
    }

    // Block reduction of dacc (deterministic).
    #pragma unroll
    for (int o = 16; o > 0; o >>= 1)
        dacc += __shfl_down_sync(0xffffffffu, dacc, o);
    if (lane == 0) dsum[w] = dacc;
    __syncthreads();
    if (tid == 0) {
        g_partial[row] = dsum[0] + dsum[1];
        __threadfence();
        unsigned int prev = atomicAdd(&g_count, 1u);
        is_last = (prev == (unsigned int)(gridDim.x - 1));
    }
    __syncthreads();

    // Last block: final deterministic reduce of 1024 partials with warp 0.
    if (is_last && w == 0) {
        if (lane == 0) g_count = 0;   // reset for graph replay
        double v = 0.0;
        #pragma unroll
        for (int j = 0; j < NROWS / 32; j++)
            v += g_partial[lane * (NROWS / 32) + j];
        #pragma unroll
        for (int o = 16; o > 0; o >>= 1)
            v += __shfl_down_sync(0xffffffffu, v, o);
        if (lane == 0) {
            double tc = (double)T_LEN * 16.0;            // T*C
            double scale = 2.0 / (tc * (tc + 1.0));
            out[0] = (float)((v / 64.0) * scale);        // mean over B=64
        }
    }
}

extern "C" void kernel_launch(void* const* d_in, const int* in_sizes, int n_in,
                              void* d_out, int out_size) {
    (void)in_sizes; (void)n_in; (void)out_size;
    const float* y_pred = (const float*)d_in[0];
    const float* y_true = (const float*)d_in[1];
    float* out = (float*)d_out;
    wass_kernel<<<NROWS, NT>>>(y_pred, y_true, out);
}